// round 1
// baseline (speedup 1.0000x reference)
#include <cuda_runtime.h>
#include <cstdint>

// PatchPermAugmentation: x (B,T,N,C)=(32,1024,512,3) fp32, perm (B, NB=512) int32.
// out[b,t,n,0] = x[b, perm[b,t/2]*2 + t%2, n, 0]; out[b,t,n,1:] = x[b,t,n,1:].
//
// Row view: a "row" is the contiguous N*C = 1536 floats at (b,t).
// For float index f within a row: channel = f%3, and the gathered ch0 value
// lives at the SAME index f in the source row. So:
//   out_row[f] = (f%3==0) ? src_row[f] : id_row[f]
// which vectorizes as per-component selects on float4 (pattern period 3 in
// float4 units: i%3==0 -> comps {x,w} from src; i%3==1 -> {z}; i%3==2 -> {y}).
//
// Uniform-per-row fast path: when src_t == t (majority of blocks; selection
// rate 0.25), it's a pure copy.

#define BB 32
#define TT 1024
#define NN 512
#define CC 3
#define PSZ 2
#define NBLK (TT / PSZ)            // 512
#define ROW_FLOATS (NN * CC)       // 1536
#define ROW_VEC4 (ROW_FLOATS / 4)  // 384

__global__ __launch_bounds__(128)
void patch_perm_kernel(const float4* __restrict__ x,
                       const int* __restrict__ perm,
                       float4* __restrict__ out) {
    const int row = blockIdx.x;          // b*T + t
    const int b = row >> 10;             // row / 1024
    const int t = row & (TT - 1);        // row % 1024
    const int blk = t >> 1;
    const int src_t = perm[b * NBLK + blk] * PSZ + (t & 1);

    const float4* __restrict__ idr = x + (size_t)row * ROW_VEC4;
    float4* __restrict__ outr = out + (size_t)row * ROW_VEC4;

    const int i0 = threadIdx.x;          // 0..127
    const int i1 = i0 + 128;
    const int i2 = i0 + 256;

    // Front-batched identity loads (MLP>=3)
    float4 v0 = idr[i0];
    float4 v1 = idr[i1];
    float4 v2 = idr[i2];

    if (src_t != t) {                    // uniform branch per CTA
        const float4* __restrict__ sr =
            x + (size_t)(b * TT + src_t) * ROW_VEC4;
        float4 s0 = sr[i0];
        float4 s1 = sr[i1];
        float4 s2 = sr[i2];

        // component selection by (float4 index) % 3
        int m0 = i0 % 3;
        if (m0 == 0)      { v0.x = s0.x; v0.w = s0.w; }
        else if (m0 == 1) { v0.z = s0.z; }
        else              { v0.y = s0.y; }

        int m1 = i1 % 3;
        if (m1 == 0)      { v1.x = s1.x; v1.w = s1.w; }
        else if (m1 == 1) { v1.z = s1.z; }
        else              { v1.y = s1.y; }

        int m2 = i2 % 3;
        if (m2 == 0)      { v2.x = s2.x; v2.w = s2.w; }
        else if (m2 == 1) { v2.z = s2.z; }
        else              { v2.y = s2.y; }
    }

    outr[i0] = v0;
    outr[i1] = v1;
    outr[i2] = v2;
}

extern "C" void kernel_launch(void* const* d_in, const int* in_sizes, int n_in,
                              void* d_out, int out_size) {
    const float4* x = (const float4*)d_in[0];
    const int* perm = (const int*)d_in[1];
    float4* out = (float4*)d_out;

    dim3 grid(BB * TT);   // 32768 rows
    dim3 block(128);
    patch_perm_kernel<<<grid, block>>>(x, perm, out);
}